// round 7
// baseline (speedup 1.0000x reference)
#include <cuda_runtime.h>

#define BB 32
#define SS 1024
#define DD 512
#define DD4 (DD/4)
#define MAXL 8192   // durations in [1,8], S=1024 -> mel_len <= 8192
#define NSCAN 256   // scanner blocks: 32 batches x 8 chunks

// Scratch (no device allocation allowed)
__device__ __align__(16) int g_idx[BB * MAXL]; // src row b*S+i, or -1 = padding
__device__ int g_done = 0;   // scanners finished
__device__ int g_fin  = 0;   // blocks finished (for per-launch reset)

// ---------------------------------------------------------------------------
// Single fused kernel.
//  Phase 1 (blocks 0..NSCAN-1): warp-shuffle scan of durations[b] -> smem csum,
//    binary-search this chunk's output rows -> g_idx (+ mask/mel_len tails),
//    release via threadfence + g_done.
//  Phase 2 (all blocks): spin (thread 0) until g_done==NSCAN, then stream:
//    ONE WARP PER OUTPUT ROW, 4x LDG.128 + 4x STG.128 (__stcs).
//  Epilogue: last block resets flags so every graph replay is identical.
// ---------------------------------------------------------------------------
__global__ __launch_bounds__(256)
void lr_fused_kernel(const int*    __restrict__ dur,
                     const float4* __restrict__ x4,
                     float4*       __restrict__ out4,
                     float*        __restrict__ mel_len_out,
                     float*        __restrict__ mask_out,
                     int max_len, int rows_pc, int has_tail,
                     int total_rows, int nblocks)
{
    __shared__ int s[SS];
    __shared__ int wsum[8];

    const int tid  = threadIdx.x;
    const int bid  = blockIdx.x;
    const int lane = tid & 31;
    const int wid  = tid >> 5;

    // ---------------- Phase 1: scan + index build (first NSCAN blocks) -----
    if (bid < NSCAN) {
        const int b     = bid >> 3;
        const int chunk = bid & 7;

        // 256 threads x 4 durations each
        const int4 d = __ldg(((const int4*)(dur + b * SS)) + tid);
        const int p0 = d.x;
        const int p1 = p0 + d.y;
        const int p2 = p1 + d.z;
        const int p3 = p2 + d.w;          // this thread's total
        int tot = p3;

        // warp inclusive scan of per-thread totals
        #pragma unroll
        for (int off = 1; off < 32; off <<= 1) {
            int n = __shfl_up_sync(0xffffffff, tot, off);
            if (lane >= off) tot += n;
        }
        if (lane == 31) wsum[wid] = tot;
        __syncthreads();
        if (wid == 0 && lane < 8) {
            int w = wsum[lane];
            #pragma unroll
            for (int off = 1; off < 8; off <<= 1) {
                int n = __shfl_up_sync(0xff, w, off);
                if (lane >= off) w += n;
            }
            wsum[lane] = w;
        }
        __syncthreads();

        const int base = (tot - p3) + ((wid > 0) ? wsum[wid - 1] : 0);
        s[4 * tid + 0] = base + p0;
        s[4 * tid + 1] = base + p1;
        s[4 * tid + 2] = base + p2;
        s[4 * tid + 3] = base + p3;
        __syncthreads();

        const int mel = s[SS - 1];
        if (has_tail && chunk == 0 && tid == 0) mel_len_out[b] = (float)mel;

        const int t0 = chunk * rows_pc;
        const int t1 = min(t0 + rows_pc, max_len);
        for (int t = t0 + tid; t < t1; t += 256) {
            const int r = b * max_len + t;
            if (t >= mel) {
                g_idx[r] = -1;
                if (has_tail) mask_out[r] = 1.0f;
            } else {
                int lo = 0, hi = SS - 1;   // first i with s[i] > t
                #pragma unroll
                for (int it = 0; it < 10; ++it) {
                    if (lo < hi) {
                        int mid = (lo + hi) >> 1;
                        if (s[mid] > t) hi = mid; else lo = mid + 1;
                    }
                }
                g_idx[r] = b * SS + lo;
                if (has_tail) mask_out[r] = 0.0f;
            }
        }
        __threadfence();
        __syncthreads();
        if (tid == 0) atomicAdd(&g_done, 1);
    }

    // ---------------- sync: wait until all scanners published ---------------
    if (tid == 0) {
        while (*((volatile int*)&g_done) < NSCAN) __nanosleep(64);
    }
    __syncthreads();

    // ---------------- Phase 2: streaming expand, one warp per row ----------
    const int row = bid * 8 + wid;
    if (row < total_rows) {
        const int  src      = __ldcg(&g_idx[row]);   // L2 read (skip stale L1)
        const long out_base = (long)row * DD4 + lane;
        if (src < 0) {
            const float4 z = make_float4(0.f, 0.f, 0.f, 0.f);
            __stcs(&out4[out_base],      z);
            __stcs(&out4[out_base + 32], z);
            __stcs(&out4[out_base + 64], z);
            __stcs(&out4[out_base + 96], z);
        } else {
            const long in_base = (long)src * DD4 + lane;
            float4 v0 = __ldg(&x4[in_base]);
            float4 v1 = __ldg(&x4[in_base + 32]);
            float4 v2 = __ldg(&x4[in_base + 64]);
            float4 v3 = __ldg(&x4[in_base + 96]);
            __stcs(&out4[out_base],      v0);
            __stcs(&out4[out_base + 32], v1);
            __stcs(&out4[out_base + 64], v2);
            __stcs(&out4[out_base + 96], v3);
        }
    }

    // ---------------- epilogue: last block resets flags for next replay ----
    __syncthreads();
    if (tid == 0) {
        const int old = atomicAdd(&g_fin, 1);
        if (old == nblocks - 1) {
            g_done = 0;
            g_fin  = 0;
            __threadfence();
        }
    }
}

// ---------------------------------------------------------------------------
extern "C" void kernel_launch(void* const* d_in, const int* in_sizes, int n_in,
                              void* d_out, int out_size)
{
    const float* x   = (const float*)d_in[0];
    const int*   dur = (const int*)d_in[1];
    float*       out = (float*)d_out;

    // Recover max_len from out_size (tuple layout vs expanded-only).
    long L;
    int has_tail;
    long os = (long)out_size;
    if ((os - BB) > 0 && ((os - BB) % ((long)BB * (DD + 1))) == 0) {
        L = (os - BB) / ((long)BB * (DD + 1));
        has_tail = 1;
    } else {
        L = os / ((long)BB * DD);
        has_tail = 0;
    }
    if (L <= 0 || L > MAXL) return;

    const int max_len = (int)L;
    const int rows_pc = (max_len + 7) / 8;            // rows per scanner chunk
    const int total_rows = BB * max_len;              // 32*L (multiple of 32)

    int nblocks = (total_rows + 7) / 8;               // one warp per row, 8/block
    if (nblocks < NSCAN) nblocks = NSCAN;             // scanners must exist

    float* mel_len_out = out + (long)BB * max_len * DD;   // B floats
    float* mask_out    = mel_len_out + BB;                // B*L floats

    lr_fused_kernel<<<nblocks, 256>>>(dur, (const float4*)x, (float4*)out,
                                      mel_len_out, mask_out,
                                      max_len, rows_pc, has_tail,
                                      total_rows, nblocks);
}

// round 8
// speedup vs baseline: 1.0656x; 1.0656x over previous
#include <cuda_runtime.h>

#define BB 32
#define SS 1024
#define DD 512
#define DD4 (DD/4)
#define MAXL 8192   // durations in [1,8], S=1024 -> mel_len <= 8192

// Scratch (no device allocation allowed)
__device__ __align__(16) int g_csum[BB * SS];   // per-batch inclusive scan
__device__ __align__(16) int g_sum32[BB * 32];  // level-1 summary: csum[b][32j+31]

// ---------------------------------------------------------------------------
// K1: pure scan. 32 blocks x 256 threads, int4 per thread.
// Writes g_csum, the 32-entry per-batch summary, and the mel_len fp32 tail.
// ---------------------------------------------------------------------------
__global__ __launch_bounds__(256)
void lr_scan_kernel(const int* __restrict__ dur,
                    float* __restrict__ mel_len_out,
                    int has_tail)
{
    __shared__ int wsum[8];
    const int b    = blockIdx.x;
    const int tid  = threadIdx.x;
    const int lane = tid & 31;
    const int wid  = tid >> 5;

    const int4 d = __ldg(((const int4*)(dur + b * SS)) + tid);
    const int p0 = d.x;
    const int p1 = p0 + d.y;
    const int p2 = p1 + d.z;
    const int p3 = p2 + d.w;
    int tot = p3;

    #pragma unroll
    for (int off = 1; off < 32; off <<= 1) {
        int n = __shfl_up_sync(0xffffffff, tot, off);
        if (lane >= off) tot += n;
    }
    if (lane == 31) wsum[wid] = tot;
    __syncthreads();
    if (wid == 0 && lane < 8) {
        int w = wsum[lane];
        #pragma unroll
        for (int off = 1; off < 8; off <<= 1) {
            int n = __shfl_up_sync(0xff, w, off);
            if (lane >= off) w += n;
        }
        wsum[lane] = w;
    }
    __syncthreads();

    const int base = (tot - p3) + ((wid > 0) ? wsum[wid - 1] : 0);
    int4 o;
    o.x = base + p0; o.y = base + p1; o.z = base + p2; o.w = base + p3;
    ((int4*)(g_csum + b * SS))[tid] = o;

    // level-1 summary: element 4*tid+3 == 32j+31  <=>  tid % 8 == 7
    if ((tid & 7) == 7) g_sum32[(b << 5) + (tid >> 3)] = o.w;

    if (has_tail && tid == 255) mel_len_out[b] = (float)o.w;
}

// ---------------------------------------------------------------------------
// K2: streaming expand, ONE WARP PER OUTPUT ROW.
// Source index via 2-level 32-ary warp search (2 dependent L1-hot 128B loads
// + 2 ballots), then 4x LDG.128 (MLP=4) + 4x STG.128 streaming stores.
// ---------------------------------------------------------------------------
__global__ __launch_bounds__(256)
void lr_expand_kernel(const float4* __restrict__ x4,
                      float4*       __restrict__ out4,
                      float*        __restrict__ mask_out,
                      int max_len, int total_rows, int has_tail)
{
    const int row  = (blockIdx.x * blockDim.x + threadIdx.x) >> 5;
    const int lane = threadIdx.x & 31;
    if (row >= total_rows) return;

    const int b = row / max_len;              // warp-uniform
    const int t = row - b * max_len;

    // level 1: 32 segment maxima (one 128B line, L1-hot)
    const int s1  = __ldg(&g_sum32[(b << 5) + lane]);
    const int mel = __shfl_sync(0xffffffff, s1, 31);

    const long out_base = (long)row * DD4 + lane;

    if (t >= mel) {                           // warp-uniform padding path
        if (has_tail && lane == 0) mask_out[row] = 1.0f;
        const float4 z = make_float4(0.f, 0.f, 0.f, 0.f);
        __stcs(&out4[out_base],      z);
        __stcs(&out4[out_base + 32], z);
        __stcs(&out4[out_base + 64], z);
        __stcs(&out4[out_base + 96], z);
        return;
    }
    if (has_tail && lane == 0) mask_out[row] = 0.0f;

    const unsigned m1  = __ballot_sync(0xffffffff, s1 > t);
    const int      seg = __ffs(m1) - 1;

    // level 2: 32 entries of the winning segment (one 128B line)
    const int s2 = __ldg(&g_csum[(b << 10) + (seg << 5) + lane]);
    const unsigned m2 = __ballot_sync(0xffffffff, s2 > t);
    const int lo = (seg << 5) + __ffs(m2) - 1;   // first i with csum[i] > t

    const long in_base = ((long)(b * SS + lo)) * DD4 + lane;
    float4 v0 = __ldg(&x4[in_base]);
    float4 v1 = __ldg(&x4[in_base + 32]);
    float4 v2 = __ldg(&x4[in_base + 64]);
    float4 v3 = __ldg(&x4[in_base + 96]);
    __stcs(&out4[out_base],      v0);
    __stcs(&out4[out_base + 32], v1);
    __stcs(&out4[out_base + 64], v2);
    __stcs(&out4[out_base + 96], v3);
}

// ---------------------------------------------------------------------------
extern "C" void kernel_launch(void* const* d_in, const int* in_sizes, int n_in,
                              void* d_out, int out_size)
{
    const float* x   = (const float*)d_in[0];
    const int*   dur = (const int*)d_in[1];
    float*       out = (float*)d_out;

    // Recover max_len from out_size (tuple layout vs expanded-only).
    long L;
    int has_tail;
    long os = (long)out_size;
    if ((os - BB) > 0 && ((os - BB) % ((long)BB * (DD + 1))) == 0) {
        L = (os - BB) / ((long)BB * (DD + 1));
        has_tail = 1;
    } else {
        L = os / ((long)BB * DD);
        has_tail = 0;
    }
    if (L <= 0 || L > MAXL) return;

    const int max_len = (int)L;
    const int total_rows = BB * max_len;

    float* mel_len_out = out + (long)BB * max_len * DD;   // B floats
    float* mask_out    = mel_len_out + BB;                // B*L floats

    // K1: scan only (tiny)
    lr_scan_kernel<<<BB, 256>>>(dur, mel_len_out, has_tail);

    // K2: expand with in-warp 2-level search
    {
        const int warps_per_block = 256 / 32;
        const int blocks = (total_rows + warps_per_block - 1) / warps_per_block;
        lr_expand_kernel<<<blocks, 256>>>((const float4*)x, (float4*)out,
                                          mask_out, max_len, total_rows, has_tail);
    }
}